// round 3
// baseline (speedup 1.0000x reference)
#include <cuda_runtime.h>

#define RES    128
#define FEAT   18
#define TPB    256
#define NWARP  (TPB / 32)
#define CBSIZE (RES * RES * RES * FEAT)   // 37748736 floats
#define WIN    40                          // floats per region window
#define PPAD   11                          // float4 chunks per point (176B: bank-conflict-free)

__global__ __launch_bounds__(TPB, 4)
void densegrid_coop_kernel(const float* __restrict__ pts,
                           const float* __restrict__ cb,
                           const float* __restrict__ T,
                           float* __restrict__ out,
                           int N)
{
    __shared__ float4 buf[NWARP][32][PPAD];   // 45056 B gather staging (reused for output)
    __shared__ int    obase[NWARP][32][4];    // 4096 B region row-start offsets

    const int tid  = threadIdx.x;
    const int w    = tid >> 5;
    const int lane = tid & 31;
    const int n    = blockIdx.x * TPB + tid;

    // ---- transform inverse (broadcast loads) ----
    const float a  = __ldg(T + 0), b  = __ldg(T + 1), c_  = __ldg(T + 2),  tx = __ldg(T + 3);
    const float d  = __ldg(T + 4), e  = __ldg(T + 5), f  = __ldg(T + 6),  ty = __ldg(T + 7);
    const float g  = __ldg(T + 8), h  = __ldg(T + 9), ii = __ldg(T + 10), tz = __ldg(T + 11);

    const float det = a * (e * ii - f * h) - b * (d * ii - f * g) + c_ * (d * h - e * g);
    const float rd  = 1.0f / det;
    const float m00 = (e * ii - f * h) * rd,  m01 = (c_ * h - b * ii) * rd,  m02 = (b * f - c_ * e) * rd;
    const float m10 = (f * g - d * ii) * rd,  m11 = (a * ii - c_ * g) * rd,  m12 = (c_ * d - a * f) * rd;
    const float m20 = (d * h - e * g) * rd,   m21 = (b * g - a * h) * rd,    m22 = (a * e - b * d) * rd;

    // ---- per-point setup ----
    float wx0 = 0.f, wx1 = 0.f, wy0 = 0.f, wy1 = 0.f, wz0 = 0.f, wz1 = 0.f;
    int o_r[4] = {0, 0, 0, 0};

    if (n < N) {
        const float qx = __ldcs(pts + 3 * n + 0) - tx;
        const float qy = __ldcs(pts + 3 * n + 1) - ty;
        const float qz = __ldcs(pts + 3 * n + 2) - tz;

        float px = (m00 * qx + m01 * qy + m02 * qz) * (float)(RES - 1);
        float py = (m10 * qx + m11 * qy + m12 * qz) * (float)(RES - 1);
        float pz = (m20 * qx + m21 * qy + m22 * qz) * (float)(RES - 1);

        const float fx = floorf(px), fy = floorf(py), fz = floorf(pz);
        wx1 = px - fx; wx0 = 1.0f - wx1;
        wy1 = py - fy; wy0 = 1.0f - wy1;
        wz1 = pz - fz; wz0 = 1.0f - wz1;

        int ix0 = max(0, min(RES - 1, (int)fx));
        int iy0 = max(0, min(RES - 1, (int)fy));
        int iz0 = max(0, min(RES - 1, (int)fz));
        const int iy1 = min(iy0 + 1, RES - 1);
        const int iz1 = min(iz0 + 1, RES - 1);
        // ix1 = ix0+1 always for in-range pts; region covers both x-corners contiguously

        #pragma unroll
        for (int r = 0; r < 4; r++) {
            const int yy = (r & 1) ? iy1 : iy0;
            const int zz = (r & 2) ? iz1 : iz0;
            o_r[r] = (ix0 + yy * RES + zz * RES * RES) * FEAT;
        }
    }

    #pragma unroll
    for (int r = 0; r < 4; r++) obase[w][lane][r] = o_r[r];

    // gather lane mapping: lane -> (chunk, point-base)
    const int  gc  = lane % 10;          // chunk index 0..9
    const int  gpb = lane / 10;          // point base 0..2 (lane 30,31 idle)
    const bool glv = (lane < 30);

    float acc[FEAT];
    #pragma unroll
    for (int j = 0; j < FEAT; j++) acc[j] = 0.0f;

    __syncwarp();

    #pragma unroll
    for (int r = 0; r < 4; r++) {
        // ---- cooperative gather: 11 LDG.128 per warp cover 32 regions x 10 chunks ----
        #pragma unroll
        for (int j = 0; j < 11; j++) {
            const int p = gpb + 3 * j;
            if (glv && p < 32) {
                const int o  = obase[w][p][r];
                const int ba = min(o & ~3, CBSIZE - WIN);   // 16B-aligned, end-clamped
                buf[w][p][gc] = __ldg((const float4*)cb + (ba >> 2) + gc);
            }
        }
        __syncwarp();

        // ---- consume own point's window from smem ----
        {
            const int   o   = o_r[r];
            const int   ba  = min(o & ~3, CBSIZE - WIN);
            const int   par = o - ba;              // 0, 2, or 4
            const bool  s0  = (par == 0);
            const bool  s1  = (par == 2);
            const float wyz = ((r & 1) ? wy1 : wy0) * ((r & 2) ? wz1 : wz0);
            const float wA  = wx0 * wyz;
            const float wB  = wx1 * wyz;

            // first half: window floats [0..23] (chunks 0..5) -> corner A (needs [par .. par+17])
            float win[24];
            #pragma unroll
            for (int k = 0; k < 6; k++) {
                const float4 q = buf[w][lane][k];
                win[4 * k + 0] = q.x; win[4 * k + 1] = q.y;
                win[4 * k + 2] = q.z; win[4 * k + 3] = q.w;
            }
            #pragma unroll
            for (int j = 0; j < FEAT; j++) {
                const float vA = s0 ? win[j] : (s1 ? win[j + 2] : win[j + 4]);
                acc[j] = fmaf(wA, vA, acc[j]);
            }

            // second half: window floats [16..39] (chunks 4..9) -> corner B (needs [par+18 .. par+35])
            #pragma unroll
            for (int k = 0; k < 6; k++) {
                const float4 q = buf[w][lane][k + 4];
                win[4 * k + 0] = q.x; win[4 * k + 1] = q.y;
                win[4 * k + 2] = q.z; win[4 * k + 3] = q.w;
            }
            // global index par+18+j == local (win base 16) index par+2+j
            #pragma unroll
            for (int j = 0; j < FEAT; j++) {
                const float vB = s0 ? win[j + 2] : (s1 ? win[j + 4] : win[j + 6]);
                acc[j] = fmaf(wB, vB, acc[j]);
            }
        }
        __syncwarp();   // before next round overwrites buf
    }

    // ---- output staging: reuse buf as a flat float array ----
    __syncthreads();
    float* stage = (float*)&buf[0][0][0];
    #pragma unroll
    for (int j = 0; j < FEAT; j++)
        stage[tid * FEAT + j] = acc[j];
    __syncthreads();

    const long long blockBase = (long long)blockIdx.x * TPB * FEAT;
    const long long remain    = (long long)N * FEAT - blockBase;

    if (remain >= (long long)TPB * FEAT) {
        const float4* s4 = (const float4*)stage;
        float4* o4 = (float4*)(out + blockBase);
        #pragma unroll
        for (int i = tid; i < TPB * FEAT / 4; i += TPB)
            __stcs(o4 + i, s4[i]);
    } else if (remain > 0) {
        float* op = out + blockBase;
        for (int i = tid; i < (int)remain; i += TPB)
            __stcs(op + i, stage[i]);
    }
}

extern "C" void kernel_launch(void* const* d_in, const int* in_sizes, int n_in,
                              void* d_out, int out_size)
{
    const float* pts = (const float*)d_in[0];
    const float* cb  = (const float*)d_in[1];
    const float* T   = (const float*)d_in[2];
    float* out       = (float*)d_out;

    const int N = in_sizes[0] / 3;
    const int blocks = (N + TPB - 1) / TPB;
    densegrid_coop_kernel<<<blocks, TPB>>>(pts, cb, T, out, N);
}